// round 13
// baseline (speedup 1.0000x reference)
#include <cuda_runtime.h>
#include <cuda_bf16.h>

#define NQ      10
#define DIM     1024
#define LAYERS  8
#define THREADS 256
#define PLANE   1088
#define CFS     8     // u64 slots/gate: [A,B,C,D,Bm,Cm,pad,pad] (64B aligned)

typedef unsigned long long u64;
#define SGN 0x8000000080000000ull

__device__ __forceinline__ int sp10(int x) {
    // suffix parity: bit p = XOR of bits p..9  (CNOT-chain permutation)
    x ^= x >> 1; x ^= x >> 2; x ^= x >> 4; x ^= x >> 8;
    return x;
}
__device__ __forceinline__ int padi(int j) { return j + 2 * (j >> 5); }

__device__ __forceinline__ u64 pfma(u64 a, u64 b, u64 c) {
    u64 d; asm("fma.rn.f32x2 %0, %1, %2, %3;" : "=l"(d) : "l"(a), "l"(b), "l"(c));
    return d;
}
__device__ __forceinline__ u64 pmul(u64 a, u64 b) {
    u64 d; asm("mul.rn.f32x2 %0, %1, %2;" : "=l"(d) : "l"(a), "l"(b));
    return d;
}
__device__ __forceinline__ u64 pack2(float lo, float hi) {
    u64 d; asm("mov.b64 %0, {%1, %2};" : "=l"(d) : "f"(lo), "f"(hi));
    return d;
}
__device__ __forceinline__ void unpack2(u64 v, float& lo, float& hi) {
    asm("mov.b64 {%0, %1}, %2;" : "=f"(lo), "=f"(hi) : "l"(v));
}
__device__ __forceinline__ u64 swap64(u64 v) {
    u64 r;
    asm("{ .reg .b32 lo, hi; mov.b64 {lo, hi}, %1; mov.b64 %0, {hi, lo}; }"
        : "=l"(r) : "l"(v));
    return r;
}
__device__ __forceinline__ u64 dup2(float v) { return pack2(v, v); }

// Lane-shuffle gate on TWO packs (4 amps). R12-validated algebra, R10 structure.
__device__ __forceinline__ void laneGate(u64& VX0, u64& VX1, u64& VY0, u64& VY1,
                                         int mask, const u64* g, u64 S, u64 Sn)
{
    const ulonglong2 ab = *(const ulonglong2*)(g);       // A, B
    const ulonglong2 cd = *(const ulonglong2*)(g + 2);   // C, D
    u64 ox0 = __shfl_xor_sync(0xffffffffu, VX0, mask);
    u64 oy0 = __shfl_xor_sync(0xffffffffu, VY0, mask);
    u64 ox1 = __shfl_xor_sync(0xffffffffu, VX1, mask);
    u64 oy1 = __shfl_xor_sync(0xffffffffu, VY1, mask);
    const u64 A  = ab.x;
    const u64 Bs = ab.y ^ S, NBs = ab.y ^ Sn;
    const u64 Cs = cd.x ^ S;
    const u64 D  = cd.y,     ND  = cd.y ^ SGN;
    u64 nx0 = pfma(A, VX0, pfma(NBs, VY0, pfma(Cs, ox0, pmul(ND, oy0))));
    u64 ny0 = pfma(A, VY0, pfma(Bs,  VX0, pfma(Cs, oy0, pmul(D,  ox0))));
    u64 nx1 = pfma(A, VX1, pfma(NBs, VY1, pfma(Cs, ox1, pmul(ND, oy1))));
    u64 ny1 = pfma(A, VY1, pfma(Bs,  VX1, pfma(Cs, oy1, pmul(D,  ox1))));
    VX0 = nx0; VY0 = ny0; VX1 = nx1; VY1 = ny1;
}

// Across-pack gate: pack0 has gate-bit 0, pack1 has 1 (R10-validated algebra).
__device__ __forceinline__ void acrossGate(u64& VX0, u64& VX1, u64& VY0, u64& VY1,
                                           const u64* g)
{
    const ulonglong2 ab = *(const ulonglong2*)(g);       // A, B
    const ulonglong2 cd = *(const ulonglong2*)(g + 2);   // C, D
    const u64 A = ab.x, B = ab.y, NB = ab.y ^ SGN;
    const u64 C = cd.x, NC = cd.x ^ SGN;
    const u64 D = cd.y, ND = cd.y ^ SGN;
    u64 nx0 = pfma(A,  VX0, pfma(NB, VY0, pfma(C, VX1, pmul(ND, VY1))));
    u64 ny0 = pfma(A,  VY0, pfma(B,  VX0, pfma(C, VY1, pmul(D,  VX1))));
    u64 nx1 = pfma(NC, VX0, pfma(ND, VY0, pfma(A, VX1, pmul(B,  VY1))));
    u64 ny1 = pfma(NC, VY0, pfma(D,  VX0, pfma(A, VY1, pmul(NB, VX1))));
    VX0 = nx0; VY0 = ny0; VX1 = nx1; VY1 = ny1;
}

// Within-pack gate (pack halves are the gate pair; R12-validated algebra).
__device__ __forceinline__ void withinGate(u64& VX0, u64& VX1, u64& VY0, u64& VY1,
                                           const u64* g)
{
    const ulonglong2 ab = *(const ulonglong2*)(g);       // A, -
    const ulonglong2 cd = *(const ulonglong2*)(g + 2);   // -, D
    const ulonglong2 ef = *(const ulonglong2*)(g + 4);   // Bm, Cm
    const u64 A = ab.x, D = cd.y, ND = cd.y ^ SGN;
    const u64 Bm = ef.x, NBm = ef.x ^ SGN, Cm = ef.y;
    u64 ox0 = swap64(VX0), oy0 = swap64(VY0);
    u64 ox1 = swap64(VX1), oy1 = swap64(VY1);
    u64 nx0 = pfma(A, VX0, pfma(NBm, VY0, pfma(Cm, ox0, pmul(ND, oy0))));
    u64 ny0 = pfma(A, VY0, pfma(Bm,  VX0, pfma(Cm, oy0, pmul(D,  ox0))));
    u64 nx1 = pfma(A, VX1, pfma(NBm, VY1, pfma(Cm, ox1, pmul(ND, oy1))));
    u64 ny1 = pfma(A, VY1, pfma(Bm,  VX1, pfma(Cm, oy1, pmul(D,  ox1))));
    VX0 = nx0; VY0 = ny0; VX1 = nx1; VY1 = ny1;
}

// outMode: 0 = real-part only (128,1024) f32; 1 = planar re-block then im-block
__global__ __launch_bounds__(THREADS)
void UnitaryR3Ansatz_kernel(const float* __restrict__ inp,
                            const float* __restrict__ params,
                            float* __restrict__ outF,
                            int outMode)
{
    const int b    = blockIdx.x;    // row 0..127
    const int copy = b >> 2;        // jnp.repeat(M, 4)
    const int t    = threadIdx.x;   // 0..255
    const int l    = t & 31;
    const int w    = t >> 5;        // 0..7

    __shared__ __align__(16) u64 cf[LAYERS][NQ][CFS];
    __shared__ float X0[PLANE], Y0[PLANE];   // A->B buffer
    __shared__ float X1[PLANE], Y1[PLANE];   // B->A buffer

    // --- coefficient tables (reference _r3 verbatim + SU(2) reduction) ---
    if (t < LAYERS * NQ) {
        const int layer = t / NQ, q = t - layer * NQ;
        const float* a = params + ((size_t)(copy * LAYERS + layer) * NQ + q) * 3;
        const float omega = a[0], theta = a[1], phi = a[2];
        float s,  c;  sincosf(0.5f * theta,         &s,  &c);
        float sp, cp; sincosf(0.5f * (phi + omega), &sp, &cp);
        float sm, cm; sincosf(0.5f * (phi - omega), &sm, &cm);
        const float m11x =  cp * c, m11y = -sp * c;   // m11 = e^{-i(phi+omega)/2} c
        const float m12x = -cm * s, m12y = -sm * s;   // m12 = -e^{+i(phi-omega)/2} s
        u64* g = cf[layer][q];
        g[0] = dup2(m11x);              // A
        g[1] = dup2(m11y);              // B
        g[2] = dup2(m12x);              // C
        g[3] = dup2(m12y);              // D
        g[4] = pack2(m11y, -m11y);      // Bm
        g[5] = pack2(m12x, -m12x);      // Cm
    }

    // --- per-thread constants (R10-validated layouts & indices) ---
    // layout A: j = [warp(3)=j9:7 | lane(5)=j6:2 | reg(2)=j1:0],  jA = 4t + r
    // layout B: j = [reg(2)=j9:8 | lane(5)=j7:3 | warp(3)=j2:0],  jB = (r<<8)|(l<<3)|w
    u64 S[5], Sn[5];
    #pragma unroll
    for (int k = 0; k < 5; ++k) {
        S[k]  = ((l >> k) & 1) ? SGN : 0ull;
        Sn[k] = S[k] ^ SGN;
    }

    const int stA0 = padi(4 * t);          // u64-aligned pair (r0,r1)
    const int stA1 = padi(4 * t + 2);      // pair (r2,r3)
    int iB[4], iE[4];
    #pragma unroll
    for (int r = 0; r < 4; ++r) {
        iB[r] = padi((r << 8) | (l << 3) | w);
        iE[r] = padi(sp10(4 * t + r));
    }

    // --- load input (layout A, coalesced float4) ---
    const float4 in4 = *(const float4*)(inp + (size_t)b * DIM + 4 * t);
    u64 VX0 = pack2(in4.x, in4.y);
    u64 VX1 = pack2(in4.z, in4.w);
    u64 VY0 = 0, VY1 = 0;

    __syncthreads();   // coefficient tables ready

    #pragma unroll 1
    for (int layer = 0; layer < LAYERS; ++layer) {
        const u64 (*G)[CFS] = cf[layer];

        // ===== layout A: q9 within, q8 across, q7..q3 on lane bits 0..4 =====
        withinGate(VX0, VX1, VY0, VY1, G[9]);
        acrossGate(VX0, VX1, VY0, VY1, G[8]);
        laneGate(VX0, VX1, VY0, VY1,  1, G[7], S[0], Sn[0]);
        laneGate(VX0, VX1, VY0, VY1,  2, G[6], S[1], Sn[1]);
        laneGate(VX0, VX1, VY0, VY1,  4, G[5], S[2], Sn[2]);
        laneGate(VX0, VX1, VY0, VY1,  8, G[4], S[3], Sn[3]);
        laneGate(VX0, VX1, VY0, VY1, 16, G[3], S[4], Sn[4]);

        // ===== remap A -> B =====
        *(u64*)(X0 + stA0) = VX0;  *(u64*)(X0 + stA1) = VX1;
        *(u64*)(Y0 + stA0) = VY0;  *(u64*)(Y0 + stA1) = VY1;
        __syncthreads();
        VX0 = pack2(X0[iB[0]], X0[iB[1]]);  VX1 = pack2(X0[iB[2]], X0[iB[3]]);
        VY0 = pack2(Y0[iB[0]], Y0[iB[1]]);  VY1 = pack2(Y0[iB[2]], Y0[iB[3]]);

        // ===== layout B: q1 within, q0 across, q2 on lane bit 4 =====
        withinGate(VX0, VX1, VY0, VY1, G[1]);
        acrossGate(VX0, VX1, VY0, VY1, G[0]);
        laneGate(VX0, VX1, VY0, VY1, 16, G[2], S[4], Sn[4]);

        // ===== remap B -> A composed with entangler =====
        {
            float f0, f1, f2, f3;
            unpack2(VX0, f0, f1); unpack2(VX1, f2, f3);
            X1[iB[0]] = f0; X1[iB[1]] = f1; X1[iB[2]] = f2; X1[iB[3]] = f3;
            unpack2(VY0, f0, f1); unpack2(VY1, f2, f3);
            Y1[iB[0]] = f0; Y1[iB[1]] = f1; Y1[iB[2]] = f2; Y1[iB[3]] = f3;
        }
        __syncthreads();
        VX0 = pack2(X1[iE[0]], X1[iE[1]]);  VX1 = pack2(X1[iE[2]], X1[iE[3]]);
        VY0 = pack2(Y1[iE[0]], Y1[iE[1]]);  VY1 = pack2(Y1[iE[2]], Y1[iE[3]]);
    }

    // --- output (layout A, coalesced float4) ---
    float x0, x1, x2, x3;
    unpack2(VX0, x0, x1); unpack2(VX1, x2, x3);
    *(float4*)(outF + (size_t)b * DIM + 4 * t) = make_float4(x0, x1, x2, x3);
    if (outMode != 0) {
        float y0, y1, y2, y3;
        unpack2(VY0, y0, y1); unpack2(VY1, y2, y3);
        *(float4*)(outF + (size_t)(128 * DIM) + (size_t)b * DIM + 4 * t) =
            make_float4(y0, y1, y2, y3);
    }
}

extern "C" void kernel_launch(void* const* d_in, const int* in_sizes, int n_in,
                              void* d_out, int out_size)
{
    const float* inp    = (const float*)d_in[0];
    const float* params = (const float*)d_in[1];
    if (n_in >= 2 && in_sizes[0] < in_sizes[1]) {
        inp    = (const float*)d_in[1];
        params = (const float*)d_in[0];
    }
    const int outMode = (out_size == 128 * DIM) ? 0 : 1;

    UnitaryR3Ansatz_kernel<<<128, THREADS>>>(inp, params, (float*)d_out, outMode);
}

// round 14
// speedup vs baseline: 1.2149x; 1.2149x over previous
#include <cuda_runtime.h>
#include <cuda_bf16.h>

#define NQ      10
#define DIM     1024
#define LAYERS  8
#define THREADS 256
#define PLANE   1088
#define CFS     8     // u64 slots/gate: [A,B,C,D,Bm,Cm,pad,pad] (64B aligned)

typedef unsigned long long u64;
#define SGN 0x8000000080000000ull

__device__ __forceinline__ int sp10(int x) {
    // suffix parity: bit p = XOR of bits p..9  (CNOT-chain permutation)
    x ^= x >> 1; x ^= x >> 2; x ^= x >> 4; x ^= x >> 8;
    return x;
}
__device__ __forceinline__ int padi(int j) { return j + 2 * (j >> 5); }

__device__ __forceinline__ u64 pfma(u64 a, u64 b, u64 c) {
    u64 d; asm("fma.rn.f32x2 %0, %1, %2, %3;" : "=l"(d) : "l"(a), "l"(b), "l"(c));
    return d;
}
__device__ __forceinline__ u64 pmul(u64 a, u64 b) {
    u64 d; asm("mul.rn.f32x2 %0, %1, %2;" : "=l"(d) : "l"(a), "l"(b));
    return d;
}
__device__ __forceinline__ u64 padd(u64 a, u64 b) {
    u64 d; asm("add.rn.f32x2 %0, %1, %2;" : "=l"(d) : "l"(a), "l"(b));
    return d;
}
__device__ __forceinline__ u64 pack2(float lo, float hi) {
    u64 d; asm("mov.b64 %0, {%1, %2};" : "=l"(d) : "f"(lo), "f"(hi));
    return d;
}
__device__ __forceinline__ void unpack2(u64 v, float& lo, float& hi) {
    asm("mov.b64 {%0, %1}, %2;" : "=f"(lo), "=f"(hi) : "l"(v));
}
__device__ __forceinline__ u64 swap64(u64 v) {
    u64 r;
    asm("{ .reg .b32 lo, hi; mov.b64 {lo, hi}, %1; mov.b64 %0, {hi, lo}; }"
        : "=l"(r) : "l"(v));
    return r;
}
__device__ __forceinline__ u64 dup2(float v) { return pack2(v, v); }

// ---- pipelined lane-gate pieces (algebra identical to validated R13) ----
__device__ __forceinline__ void laneShfl(u64 VX, u64 VY, int mask, u64& ox, u64& oy)
{
    ox = __shfl_xor_sync(0xffffffffu, VX, mask);
    oy = __shfl_xor_sync(0xffffffffu, VY, mask);
}

// Split-chain compute: v-half independent of the shuffle results.
//   VX' = (A vx + NBs vy) + (Cs ox + ND oy)
//   VY' = (A vy + Bs  vx) + (Cs oy + D  ox)
__device__ __forceinline__ void laneCompute(u64& VX, u64& VY, u64 ox, u64 oy,
                                            const u64* g, u64 S, u64 Sn)
{
    const ulonglong2 ab = *(const ulonglong2*)(g);       // A, B
    const ulonglong2 cd = *(const ulonglong2*)(g + 2);   // C, D
    const u64 A  = ab.x;
    const u64 Bs = ab.y ^ S, NBs = ab.y ^ Sn;
    const u64 Cs = cd.x ^ S;
    const u64 D  = cd.y,     ND  = cd.y ^ SGN;
    u64 prex  = pfma(A,  VX, pmul(NBs, VY));
    u64 prey  = pfma(A,  VY, pmul(Bs,  VX));
    u64 postx = pfma(Cs, ox, pmul(ND,  oy));
    u64 posty = pfma(Cs, oy, pmul(D,   ox));
    VX = padd(prex, postx);
    VY = padd(prey, posty);
}

// Across-pack gate (R13-validated).
__device__ __forceinline__ void acrossGate(u64& VX0, u64& VX1, u64& VY0, u64& VY1,
                                           const u64* g)
{
    const ulonglong2 ab = *(const ulonglong2*)(g);
    const ulonglong2 cd = *(const ulonglong2*)(g + 2);
    const u64 A = ab.x, B = ab.y, NB = ab.y ^ SGN;
    const u64 C = cd.x, NC = cd.x ^ SGN;
    const u64 D = cd.y, ND = cd.y ^ SGN;
    u64 nx0 = pfma(A,  VX0, pfma(NB, VY0, pfma(C, VX1, pmul(ND, VY1))));
    u64 ny0 = pfma(A,  VY0, pfma(B,  VX0, pfma(C, VY1, pmul(D,  VX1))));
    u64 nx1 = pfma(NC, VX0, pfma(ND, VY0, pfma(A, VX1, pmul(B,  VY1))));
    u64 ny1 = pfma(NC, VY0, pfma(D,  VX0, pfma(A, VY1, pmul(NB, VX1))));
    VX0 = nx0; VY0 = ny0; VX1 = nx1; VY1 = ny1;
}

// Within-pack gate (R13-validated).
__device__ __forceinline__ void withinGate(u64& VX0, u64& VX1, u64& VY0, u64& VY1,
                                           const u64* g)
{
    const ulonglong2 ab = *(const ulonglong2*)(g);
    const ulonglong2 cd = *(const ulonglong2*)(g + 2);
    const ulonglong2 ef = *(const ulonglong2*)(g + 4);
    const u64 A = ab.x, D = cd.y, ND = cd.y ^ SGN;
    const u64 Bm = ef.x, NBm = ef.x ^ SGN, Cm = ef.y;
    u64 ox0 = swap64(VX0), oy0 = swap64(VY0);
    u64 ox1 = swap64(VX1), oy1 = swap64(VY1);
    u64 nx0 = pfma(A, VX0, pfma(NBm, VY0, pfma(Cm, ox0, pmul(ND, oy0))));
    u64 ny0 = pfma(A, VY0, pfma(Bm,  VX0, pfma(Cm, oy0, pmul(D,  ox0))));
    u64 nx1 = pfma(A, VX1, pfma(NBm, VY1, pfma(Cm, ox1, pmul(ND, oy1))));
    u64 ny1 = pfma(A, VY1, pfma(Bm,  VX1, pfma(Cm, oy1, pmul(D,  ox1))));
    VX0 = nx0; VY0 = ny0; VX1 = nx1; VY1 = ny1;
}

// outMode: 0 = real-part only (128,1024) f32; 1 = planar re-block then im-block
__global__ __launch_bounds__(THREADS)
void UnitaryR3Ansatz_kernel(const float* __restrict__ inp,
                            const float* __restrict__ params,
                            float* __restrict__ outF,
                            int outMode)
{
    const int b    = blockIdx.x;    // row 0..127
    const int copy = b >> 2;        // jnp.repeat(M, 4)
    const int t    = threadIdx.x;   // 0..255
    const int l    = t & 31;
    const int w    = t >> 5;        // 0..7

    __shared__ __align__(16) u64 cf[LAYERS][NQ][CFS];
    __shared__ float X0[PLANE], Y0[PLANE];   // A->B buffer
    __shared__ float X1[PLANE], Y1[PLANE];   // B->A buffer

    // --- coefficient tables (reference _r3 verbatim + SU(2) reduction) ---
    if (t < LAYERS * NQ) {
        const int layer = t / NQ, q = t - layer * NQ;
        const float* a = params + ((size_t)(copy * LAYERS + layer) * NQ + q) * 3;
        const float omega = a[0], theta = a[1], phi = a[2];
        float s,  c;  sincosf(0.5f * theta,         &s,  &c);
        float sp, cp; sincosf(0.5f * (phi + omega), &sp, &cp);
        float sm, cm; sincosf(0.5f * (phi - omega), &sm, &cm);
        const float m11x =  cp * c, m11y = -sp * c;   // m11 = e^{-i(phi+omega)/2} c
        const float m12x = -cm * s, m12y = -sm * s;   // m12 = -e^{+i(phi-omega)/2} s
        u64* g = cf[layer][q];
        g[0] = dup2(m11x);              // A
        g[1] = dup2(m11y);              // B
        g[2] = dup2(m12x);              // C
        g[3] = dup2(m12y);              // D
        g[4] = pack2(m11y, -m11y);      // Bm
        g[5] = pack2(m12x, -m12x);      // Cm
    }

    // --- per-thread constants (R13-validated layouts & indices) ---
    // layout A: j = [warp(3)=j9:7 | lane(5)=j6:2 | reg(2)=j1:0],  jA = 4t + r
    // layout B: j = [reg(2)=j9:8 | lane(5)=j7:3 | warp(3)=j2:0]
    u64 S[5], Sn[5];
    #pragma unroll
    for (int k = 0; k < 5; ++k) {
        S[k]  = ((l >> k) & 1) ? SGN : 0ull;
        Sn[k] = S[k] ^ SGN;
    }

    const int stA0 = padi(4 * t);
    const int stA1 = padi(4 * t + 2);
    int iB[4], iE[4];
    #pragma unroll
    for (int r = 0; r < 4; ++r) {
        iB[r] = padi((r << 8) | (l << 3) | w);
        iE[r] = padi(sp10(4 * t + r));
    }

    // --- load input (layout A, coalesced float4) ---
    const float4 in4 = *(const float4*)(inp + (size_t)b * DIM + 4 * t);
    u64 VX0 = pack2(in4.x, in4.y);
    u64 VX1 = pack2(in4.z, in4.w);
    u64 VY0 = 0, VY1 = 0;

    __syncthreads();   // coefficient tables ready

    #pragma unroll 1
    for (int layer = 0; layer < LAYERS; ++layer) {
        const u64 (*G)[CFS] = cf[layer];

        // ===== layout A: q9 within, q8 across, then 5 pipelined lane gates =====
        withinGate(VX0, VX1, VY0, VY1, G[9]);
        acrossGate(VX0, VX1, VY0, VY1, G[8]);

        // software pipeline: pack0 one gate ahead of pack1
        u64 ox0, oy0, ox1, oy1;
        laneShfl(VX0, VY0, 1, ox0, oy0);
        laneShfl(VX1, VY1, 1, ox1, oy1);
        #pragma unroll
        for (int k = 0; k < 5; ++k) {
            laneCompute(VX0, VY0, ox0, oy0, G[7 - k], S[k], Sn[k]);
            if (k < 4) laneShfl(VX0, VY0, 2 << k, ox0, oy0);
            laneCompute(VX1, VY1, ox1, oy1, G[7 - k], S[k], Sn[k]);
            if (k < 4) laneShfl(VX1, VY1, 2 << k, ox1, oy1);
        }

        // ===== remap A -> B =====
        *(u64*)(X0 + stA0) = VX0;  *(u64*)(X0 + stA1) = VX1;
        *(u64*)(Y0 + stA0) = VY0;  *(u64*)(Y0 + stA1) = VY1;
        __syncthreads();
        VX0 = pack2(X0[iB[0]], X0[iB[1]]);  VX1 = pack2(X0[iB[2]], X0[iB[3]]);
        VY0 = pack2(Y0[iB[0]], Y0[iB[1]]);  VY1 = pack2(Y0[iB[2]], Y0[iB[3]]);

        // ===== layout B: q1 within, q0 across, q2 lane (pipelined pair) =====
        withinGate(VX0, VX1, VY0, VY1, G[1]);
        acrossGate(VX0, VX1, VY0, VY1, G[0]);
        laneShfl(VX0, VY0, 16, ox0, oy0);
        laneShfl(VX1, VY1, 16, ox1, oy1);
        laneCompute(VX0, VY0, ox0, oy0, G[2], S[4], Sn[4]);
        laneCompute(VX1, VY1, ox1, oy1, G[2], S[4], Sn[4]);

        // ===== remap B -> A composed with entangler =====
        {
            float f0, f1, f2, f3;
            unpack2(VX0, f0, f1); unpack2(VX1, f2, f3);
            X1[iB[0]] = f0; X1[iB[1]] = f1; X1[iB[2]] = f2; X1[iB[3]] = f3;
            unpack2(VY0, f0, f1); unpack2(VY1, f2, f3);
            Y1[iB[0]] = f0; Y1[iB[1]] = f1; Y1[iB[2]] = f2; Y1[iB[3]] = f3;
        }
        __syncthreads();
        VX0 = pack2(X1[iE[0]], X1[iE[1]]);  VX1 = pack2(X1[iE[2]], X1[iE[3]]);
        VY0 = pack2(Y1[iE[0]], Y1[iE[1]]);  VY1 = pack2(Y1[iE[2]], Y1[iE[3]]);
    }

    // --- output (layout A, coalesced float4) ---
    float x0, x1, x2, x3;
    unpack2(VX0, x0, x1); unpack2(VX1, x2, x3);
    *(float4*)(outF + (size_t)b * DIM + 4 * t) = make_float4(x0, x1, x2, x3);
    if (outMode != 0) {
        float y0, y1, y2, y3;
        unpack2(VY0, y0, y1); unpack2(VY1, y2, y3);
        *(float4*)(outF + (size_t)(128 * DIM) + (size_t)b * DIM + 4 * t) =
            make_float4(y0, y1, y2, y3);
    }
}

extern "C" void kernel_launch(void* const* d_in, const int* in_sizes, int n_in,
                              void* d_out, int out_size)
{
    const float* inp    = (const float*)d_in[0];
    const float* params = (const float*)d_in[1];
    if (n_in >= 2 && in_sizes[0] < in_sizes[1]) {
        inp    = (const float*)d_in[1];
        params = (const float*)d_in[0];
    }
    const int outMode = (out_size == 128 * DIM) ? 0 : 1;

    UnitaryR3Ansatz_kernel<<<128, THREADS>>>(inp, params, (float*)d_out, outMode);
}